// round 1
// baseline (speedup 1.0000x reference)
#include <cuda_runtime.h>

// Problem constants
#define B_SZ     4
#define L_SZ     4096
#define T_TOK    (B_SZ * L_SZ)   // 16384 tokens
#define D_DIM    2048
#define E_EXP    64
#define AUX_W    0.01f

// GEMM tiling
#define BM       128
#define BK       32
#define TM       8
#define TN       4
#define THREADS  256
#define XPAD     (BM + 4)        // 132 floats per k-row of X tile (16B-aligned rows)
#define WPAD     (E_EXP + 4)     // 68  floats per k-row of W tile
#define LPAD     (E_EXP + 4)     // 68  floats per logits row

// Global scratch (allocation-free rule: __device__ globals)
__device__ float g_prob_sum[E_EXP];
__device__ int   g_top1_cnt[E_EXP];

__global__ void zero_kernel() {
    int e = threadIdx.x;
    g_prob_sum[e] = 0.0f;
    g_top1_cnt[e] = 0;
}

__global__ __launch_bounds__(THREADS) void router_kernel(
    const float* __restrict__ X,   // [T_TOK, D]
    const float* __restrict__ W,   // [E, D]
    float* __restrict__ out)       // [2T indices | 2T weights | 1 aux]
{
    // smem: during GEMM holds sX[BK][XPAD] (4224 f) + sW[BK][WPAD] (2176 f);
    // after GEMM reused as logits [BM][LPAD] (8704 f).
    __shared__ __align__(16) float smem[BM * LPAD];
    __shared__ int sCnt[E_EXP];

    float* sX = smem;                  // [BK][XPAD]
    float* sW = smem + BK * XPAD;      // [BK][WPAD]

    const int tid = threadIdx.x;
    const int tx  = tid & 15;          // expert group: experts [tx*4, tx*4+4)
    const int ty  = tid >> 4;          // token group:  tokens  [ty*8, ty*8+8)
    const int m0  = blockIdx.x * BM;
    const float* Xblk = X + (size_t)m0 * D_DIM;

    float acc[TM][TN];
    #pragma unroll
    for (int i = 0; i < TM; i++)
        #pragma unroll
        for (int j = 0; j < TN; j++) acc[i][j] = 0.0f;

    for (int kt = 0; kt < D_DIM; kt += BK) {
        // Load X tile [BM x BK] transposed into sX[kk][m]
        #pragma unroll
        for (int r = 0; r < 4; r++) {
            int idx = tid + r * THREADS;        // 0..1023 float4 slots
            int m   = idx >> 3;
            int c4  = idx & 7;
            float4 v = *(const float4*)(Xblk + (size_t)m * D_DIM + kt + c4 * 4);
            int kk = c4 * 4;
            sX[(kk + 0) * XPAD + m] = v.x;
            sX[(kk + 1) * XPAD + m] = v.y;
            sX[(kk + 2) * XPAD + m] = v.z;
            sX[(kk + 3) * XPAD + m] = v.w;
        }
        // Load W tile [E x BK] transposed into sW[kk][e]
        #pragma unroll
        for (int r = 0; r < 2; r++) {
            int idx = tid + r * THREADS;        // 0..511 float4 slots
            int e   = idx >> 3;
            int c4  = idx & 7;
            float4 v = *(const float4*)(W + (size_t)e * D_DIM + kt + c4 * 4);
            int kk = c4 * 4;
            sW[(kk + 0) * WPAD + e] = v.x;
            sW[(kk + 1) * WPAD + e] = v.y;
            sW[(kk + 2) * WPAD + e] = v.z;
            sW[(kk + 3) * WPAD + e] = v.w;
        }
        __syncthreads();

        #pragma unroll
        for (int kk = 0; kk < BK; kk++) {
            float4 a0 = *(const float4*)&sX[kk * XPAD + ty * TM];
            float4 a1 = *(const float4*)&sX[kk * XPAD + ty * TM + 4];
            float4 bv = *(const float4*)&sW[kk * WPAD + tx * TN];
            float a[TM] = {a0.x, a0.y, a0.z, a0.w, a1.x, a1.y, a1.z, a1.w};
            float b[TN] = {bv.x, bv.y, bv.z, bv.w};
            #pragma unroll
            for (int i = 0; i < TM; i++)
                #pragma unroll
                for (int j = 0; j < TN; j++)
                    acc[i][j] = fmaf(a[i], b[j], acc[i][j]);
        }
        __syncthreads();
    }

    // Write logits into smem (reuse), experts contiguous per token row.
    #pragma unroll
    for (int i = 0; i < TM; i++) {
        float4 v = make_float4(acc[i][0], acc[i][1], acc[i][2], acc[i][3]);
        *(float4*)&smem[(ty * TM + i) * LPAD + tx * TN] = v;
    }
    if (tid < E_EXP) sCnt[tid] = 0;
    __syncthreads();

    // Per-token epilogue: one thread per token (threads 0..127)
    if (tid < BM) {
        float* row = &smem[tid * LPAD];
        float l1 = -1e30f, l2 = -1e30f;
        int   i1 = 0,      i2 = 0;
        #pragma unroll
        for (int e = 0; e < E_EXP; e++) {
            float v = row[e];
            if (v > l1)      { l2 = l1; i2 = i1; l1 = v; i1 = e; }
            else if (v > l2) { l2 = v;  i2 = e; }
        }
        // Full softmax probs (in-place), for aux loss
        float s = 0.0f;
        #pragma unroll
        for (int e = 0; e < E_EXP; e++) {
            float p = __expf(row[e] - l1);
            s += p;
            row[e] = p;
        }
        float inv = 1.0f / s;
        #pragma unroll
        for (int e = 0; e < E_EXP; e++) row[e] *= inv;

        // Top-2 renormalized weights: softmax([l1, l2])
        float e2 = __expf(l2 - l1);
        float d  = 1.0f / (1.0f + e2);
        float w1 = d;
        float w2 = e2 * d;

        int gm = m0 + tid;
        out[2 * gm + 0] = (float)i1;
        out[2 * gm + 1] = (float)i2;
        out[2 * T_TOK + 2 * gm + 0] = w1;
        out[2 * T_TOK + 2 * gm + 1] = w2;
        atomicAdd(&sCnt[i1], 1);
    }
    __syncthreads();

    // Per-expert column reduction over this CTA's 128 tokens, one global atomic each.
    if (tid < E_EXP) {
        float s = 0.0f;
        #pragma unroll 8
        for (int m = 0; m < BM; m++) s += smem[m * LPAD + tid];
        atomicAdd(&g_prob_sum[tid], s);
        atomicAdd(&g_top1_cnt[tid], sCnt[tid]);
    }
}

__global__ void finalize_kernel(float* __restrict__ out) {
    __shared__ float red[E_EXP];
    int e = threadIdx.x;
    float inv = 1.0f / (float)T_TOK;
    red[e] = ((float)g_top1_cnt[e] * inv) * (g_prob_sum[e] * inv);
    __syncthreads();
    #pragma unroll
    for (int s = 32; s > 0; s >>= 1) {
        if (e < s) red[e] += red[e + s];
        __syncthreads();
    }
    if (e == 0) out[4 * T_TOK] = (float)E_EXP * AUX_W * red[0];
}

extern "C" void kernel_launch(void* const* d_in, const int* in_sizes, int n_in,
                              void* d_out, int out_size) {
    const float* X = (const float*)d_in[0];   // [4,4096,2048] f32
    const float* W = (const float*)d_in[1];   // [64,2048] f32
    float* out = (float*)d_out;

    zero_kernel<<<1, E_EXP>>>();
    router_kernel<<<T_TOK / BM, THREADS>>>(X, W, out);
    finalize_kernel<<<1, E_EXP>>>(out);
}

// round 3
// speedup vs baseline: 1.6169x; 1.6169x over previous
#include <cuda_runtime.h>
#include <cstdint>

// ---------------- problem constants ----------------
#define T_TOK   16384
#define D_DIM   2048
#define E_EXP   64
#define AUX_W   0.01f

#define BM      128
#define BK      32
#define NCHUNK  (D_DIM / BK)        // 64
#define THREADS 256
#define NCTA    (T_TOK / BM)        // 128

#define XS_STRIDE 36                // 32 + 4 pad (floats)
#define STAGE_F   (BM * XS_STRIDE + E_EXP * XS_STRIDE)   // 6912 floats per stage
#define XTILE_F   (BM * XS_STRIDE)                       // 4608 floats
#define LPAD      68
#define DYN_SMEM  (2 * STAGE_F * 4)                      // 55296 bytes

// ---------------- global scratch ----------------
__device__ float    g_psum[NCTA * E_EXP];
__device__ float    g_pcnt[NCTA * E_EXP];
__device__ unsigned g_done = 0;

// ---------------- helpers ----------------
__device__ __forceinline__ uint32_t smem_u32(const void* p) {
    uint32_t a;
    asm("{ .reg .u64 t; cvta.to.shared.u64 t, %1; cvt.u32.u64 %0, t; }" : "=r"(a) : "l"(p));
    return a;
}
__device__ __forceinline__ void cvt_hilo(float x, uint32_t& hi, uint32_t& lo) {
    uint32_t h;
    asm("cvt.rna.tf32.f32 %0, %1;" : "=r"(h) : "f"(x));
    float r = x - __uint_as_float(h);
    uint32_t l;
    asm("cvt.rna.tf32.f32 %0, %1;" : "=r"(l) : "f"(r));
    hi = h; lo = l;
}
#define CP_ASYNC16(saddr, gptr) \
    asm volatile("cp.async.cg.shared.global [%0], [%1], 16;" :: "r"(saddr), "l"(gptr) : "memory")
#define CP_COMMIT() asm volatile("cp.async.commit_group;" ::: "memory")
#define CP_WAIT(n)  asm volatile("cp.async.wait_group %0;" :: "n"(n) : "memory")

#define MMA_TF32(c, a, b) \
    asm volatile("mma.sync.aligned.m16n8k8.row.col.f32.tf32.tf32.f32 " \
        "{%0,%1,%2,%3}, {%4,%5,%6,%7}, {%8,%9}, {%0,%1,%2,%3};" \
        : "+f"((c)[0]), "+f"((c)[1]), "+f"((c)[2]), "+f"((c)[3]) \
        : "r"((a)[0]), "r"((a)[1]), "r"((a)[2]), "r"((a)[3]), "r"((b)[0]), "r"((b)[1]))

extern __shared__ __align__(16) float Sf[];

__global__ __launch_bounds__(THREADS, 1) void router_kernel(
    const float* __restrict__ X,   // [T_TOK, D]
    const float* __restrict__ W,   // [E, D]
    float* __restrict__ out)       // [2T idx | 2T w | 1 aux]
{
    __shared__ int   sCnt[E_EXP];
    __shared__ float sRed[E_EXP];
    __shared__ unsigned s_last;

    const int tid  = threadIdx.x;
    const int lane = tid & 31;
    const int wrp  = tid >> 5;        // 0..7
    const int warpM = wrp >> 1;       // 0..3  -> token rows [warpM*32, +32)
    const int warpN = wrp & 1;        // 0..1  -> experts    [warpN*32, +32)
    const int quad  = lane >> 2;      // 0..7
    const int qt    = lane & 3;       // 0..3
    const int bid = blockIdx.x;
    const int m0  = bid * BM;

    const float* Xp = X + (size_t)m0 * D_DIM;
    const uint32_t sbase = smem_u32(Sf);

    // per-thread cp.async slots
    int xrow[4], xc4[4], wrow[2], wc4[2];
#pragma unroll
    for (int r = 0; r < 4; r++) { int s = tid + r * THREADS; xrow[r] = s >> 3; xc4[r] = s & 7; }
#pragma unroll
    for (int r = 0; r < 2; r++) { int s = tid + r * THREADS; wrow[r] = s >> 3; wc4[r] = s & 7; }

    auto issue_chunk = [&](int i) {
        const int kt = i * BK;
        const uint32_t st = sbase + (uint32_t)(i & 1) * (STAGE_F * 4);
#pragma unroll
        for (int r = 0; r < 4; r++) {
            const float* g = Xp + (size_t)xrow[r] * D_DIM + kt + xc4[r] * 4;
            CP_ASYNC16(st + (uint32_t)xrow[r] * (XS_STRIDE * 4) + (uint32_t)xc4[r] * 16u, g);
        }
#pragma unroll
        for (int r = 0; r < 2; r++) {
            const float* g = W + (size_t)wrow[r] * D_DIM + kt + wc4[r] * 4;
            CP_ASYNC16(st + (uint32_t)(XTILE_F * 4) + (uint32_t)wrow[r] * (XS_STRIDE * 4) + (uint32_t)wc4[r] * 16u, g);
        }
        CP_COMMIT();
    };

    float c[2][4][4];
#pragma unroll
    for (int mi = 0; mi < 2; mi++)
#pragma unroll
        for (int ni = 0; ni < 4; ni++)
#pragma unroll
            for (int r = 0; r < 4; r++) c[mi][ni][r] = 0.0f;

    issue_chunk(0);
    issue_chunk(1);

#pragma unroll 1
    for (int i = 0; i < NCHUNK; i++) {
        if (i < NCHUNK - 1) { CP_WAIT(1); } else { CP_WAIT(0); }
        __syncthreads();

        const float* Xs = Sf + (i & 1) * STAGE_F;
        const float* Ws = Xs + XTILE_F;

#pragma unroll
        for (int k8 = 0; k8 < BK / 8; k8++) {
            const int k0 = k8 * 8;
            uint32_t ahi[2][4], alo[2][4], bhi[4][2], blo[4][2];
#pragma unroll
            for (int mi = 0; mi < 2; mi++) {
                const float* ap = Xs + (warpM * 32 + mi * 16 + quad) * XS_STRIDE + k0 + qt;
                float a0 = ap[0];
                float a1 = ap[8 * XS_STRIDE];
                float a2 = ap[4];
                float a3 = ap[8 * XS_STRIDE + 4];
                cvt_hilo(a0, ahi[mi][0], alo[mi][0]);
                cvt_hilo(a1, ahi[mi][1], alo[mi][1]);
                cvt_hilo(a2, ahi[mi][2], alo[mi][2]);
                cvt_hilo(a3, ahi[mi][3], alo[mi][3]);
            }
#pragma unroll
            for (int ni = 0; ni < 4; ni++) {
                const float* bp = Ws + (warpN * 32 + ni * 8 + quad) * XS_STRIDE + k0 + qt;
                float b0 = bp[0];
                float b1 = bp[4];
                cvt_hilo(b0, bhi[ni][0], blo[ni][0]);
                cvt_hilo(b1, bhi[ni][1], blo[ni][1]);
            }
            // pass 1: hi*hi
#pragma unroll
            for (int mi = 0; mi < 2; mi++)
#pragma unroll
                for (int ni = 0; ni < 4; ni++) MMA_TF32(c[mi][ni], ahi[mi], bhi[ni]);
            // pass 2: hi*lo
#pragma unroll
            for (int mi = 0; mi < 2; mi++)
#pragma unroll
                for (int ni = 0; ni < 4; ni++) MMA_TF32(c[mi][ni], ahi[mi], blo[ni]);
            // pass 3: lo*hi
#pragma unroll
            for (int mi = 0; mi < 2; mi++)
#pragma unroll
                for (int ni = 0; ni < 4; ni++) MMA_TF32(c[mi][ni], alo[mi], bhi[ni]);
        }
        __syncthreads();
        if (i + 2 < NCHUNK) issue_chunk(i + 2);
    }

    // ---------- write logits to smem (reuse stage buffers) ----------
    if (tid < E_EXP) sCnt[tid] = 0;
#pragma unroll
    for (int mi = 0; mi < 2; mi++)
#pragma unroll
        for (int ni = 0; ni < 4; ni++) {
            int row = warpM * 32 + mi * 16 + quad;
            int col = warpN * 32 + ni * 8 + 2 * qt;
            *(float2*)&Sf[row * LPAD + col]       = make_float2(c[mi][ni][0], c[mi][ni][1]);
            *(float2*)&Sf[(row + 8) * LPAD + col] = make_float2(c[mi][ni][2], c[mi][ni][3]);
        }
    __syncthreads();

    // ---------- per-token epilogue ----------
    if (tid < BM) {
        const float* row = &Sf[tid * LPAD];
        float v[E_EXP];
#pragma unroll
        for (int j = 0; j < E_EXP / 4; j++) {
            float4 q = *(const float4*)&row[4 * j];
            v[4 * j] = q.x; v[4 * j + 1] = q.y; v[4 * j + 2] = q.z; v[4 * j + 3] = q.w;
        }
        float l1 = -1e30f, l2 = -1e30f;
        int   i1 = 0,      i2 = 0;
#pragma unroll
        for (int e = 0; e < E_EXP; e++) {
            float x = v[e];
            if (x > l1)      { l2 = l1; i2 = i1; l1 = x; i1 = e; }
            else if (x > l2) { l2 = x;  i2 = e; }
        }
        float ssum = 0.0f;
#pragma unroll
        for (int e = 0; e < E_EXP; e++) { float p = __expf(v[e] - l1); ssum += p; v[e] = p; }
        float inv = 1.0f / ssum;

        float e2 = __expf(l2 - l1);
        float dn = 1.0f / (1.0f + e2);
        int gm = m0 + tid;
        out[2 * gm + 0] = (float)i1;
        out[2 * gm + 1] = (float)i2;
        out[2 * T_TOK + 2 * gm + 0] = dn;
        out[2 * T_TOK + 2 * gm + 1] = e2 * dn;
        atomicAdd(&sCnt[i1], 1);
        // normalized probs back to smem for column reduction (packed 64-wide)
        __syncthreads();  // all reads of logits done before overwrite
#pragma unroll
        for (int j = 0; j < E_EXP / 4; j++) {
            float4 q = make_float4(v[4 * j] * inv, v[4 * j + 1] * inv, v[4 * j + 2] * inv, v[4 * j + 3] * inv);
            *(float4*)&Sf[tid * E_EXP + 4 * j] = q;
        }
    } else {
        __syncthreads();
    }
    __syncthreads();

    // ---------- per-expert partials ----------
    if (tid < E_EXP) {
        float s = 0.0f;
#pragma unroll 8
        for (int m = 0; m < BM; m++) s += Sf[m * E_EXP + tid];
        g_psum[bid * E_EXP + tid] = s;
        g_pcnt[bid * E_EXP + tid] = (float)sCnt[tid];
    }
    __threadfence();
    __syncthreads();

    if (tid == 0) s_last = (atomicInc(&g_done, NCTA - 1) == NCTA - 1) ? 1u : 0u;
    __syncthreads();

    if (s_last) {
        __threadfence();
        if (tid < E_EXP) {
            float a = 0.0f, cn = 0.0f;
#pragma unroll 8
            for (int b = 0; b < NCTA; b++) {
                a  += __ldcg(&g_psum[b * E_EXP + tid]);
                cn += __ldcg(&g_pcnt[b * E_EXP + tid]);
            }
            float invT = 1.0f / (float)T_TOK;
            sRed[tid] = (cn * invT) * (a * invT);
        }
        __syncthreads();
        if (tid < 32) {
            float vv = sRed[tid] + sRed[tid + 32];
#pragma unroll
            for (int o = 16; o > 0; o >>= 1) vv += __shfl_xor_sync(0xFFFFFFFF, vv, o);
            if (tid == 0) out[4 * T_TOK] = (float)E_EXP * AUX_W * vv;
        }
    }
}

extern "C" void kernel_launch(void* const* d_in, const int* in_sizes, int n_in,
                              void* d_out, int out_size) {
    const float* X = (const float*)d_in[0];
    const float* W = (const float*)d_in[1];
    float* out = (float*)d_out;

    cudaFuncSetAttribute(router_kernel, cudaFuncAttributeMaxDynamicSharedMemorySize, DYN_SMEM);
    router_kernel<<<NCTA, THREADS, DYN_SMEM>>>(X, W, out);
}